// round 14
// baseline (speedup 1.0000x reference)
#include <cuda_runtime.h>
#include <cstdint>

#define WIRE_DIM 32
#define NUM_WIRES 64
#define ROW_ELEMS (NUM_WIRES * WIRE_DIM)   // 2048
#define HALF_PAD 36                         // wire stride in smem floats (conflict-free LDS.128)
#define WARPS_PER_BLOCK 4                   // 2 rows/block, 2 warps per row
#define ROWS_PER_BLOCK 2
#define THREADS (32 * WARPS_PER_BLOCK)

// packed fp32x2 FMA (SASS FFMA2)
#define FMA_F32X2(d, a, b, c) \
    asm("fma.rn.f32x2 %0, %1, %2, %3;" : "=l"(d) : "l"(a), "l"(b), "l"(c))

__device__ __forceinline__ float2 upk2(uint64_t v) {
    float2 r; asm("mov.b64 {%0, %1}, %2;" : "=f"(r.x), "=f"(r.y) : "l"(v)); return r;
}

__global__ __launch_bounds__(THREADS)
void isinone_loss_kernel(const float* __restrict__ outputs,
                         const int* __restrict__ tests,      // int32 pairs (person, location)
                         const float* __restrict__ W1,
                         const float* __restrict__ b1,
                         const float* __restrict__ W2,
                         const float* __restrict__ b2,
                         float* __restrict__ out,
                         int B)
{
    // W1 bottom rows transposed, k-contiguous per h: s_w1b[h*32+k] = W1[(32+k)*10+h]
    __shared__ __align__(16) float s_w1b[10 * 32];
    // W1 top rows, original [k][h] layout (conflict-free lane reads for person proj)
    __shared__ __align__(16) float s_w1top[320];
    // half-row staging: each warp owns 32 wires
    __shared__ __align__(16) float s_half[WARPS_PER_BLOCK][32 * HALF_PAD];
    __shared__ float s_w2[10];
    __shared__ float s_b2;
    __shared__ float s_aw[ROWS_PER_BLOCK][10];   // b1 + person_vec @ W1_top (per row)
    __shared__ float s_m[WARPS_PER_BLOCK];       // per-warp logit max
    __shared__ float s_s[WARPS_PER_BLOCK];       // per-warp exp-sum
    __shared__ float s_sel[ROWS_PER_BLOCK];      // selected logit

    const int tid = threadIdx.x;

    // ---- load weights (once per block) ----
    for (int i = tid; i < 320; i += THREADS) {
        s_w1top[i] = W1[i];                    // first 32 rows, as-is
        int h = i >> 5, k = i & 31;
        s_w1b[h * 32 + k] = W1[(32 + k) * 10 + h];
    }
    if (tid < 10) s_w2[tid] = W2[tid];
    if (tid == 0) s_b2 = b2[0];
    __syncthreads();

    const int warp   = tid >> 5;
    const int lane   = tid & 31;
    const int rowloc = warp >> 1;              // row within block (0/1)
    const int half   = warp & 1;               // which 32-wire half this warp owns
    const int row    = blockIdx.x * ROWS_PER_BLOCK + rowloc;
    const bool active = (row < B);

    float l = 0.f;
    int loc = 0;

    if (active) {
        const float*  grow  = outputs + (size_t)row * ROW_ELEMS;
        const float4* grow4 = (const float4*)grow;
        float* sh = s_half[warp];

        const int p = tests[2 * row + 0];
        loc = tests[2 * row + 1];

        // ---- stage this half-row: wires [half*32, half*32+32) ----
#pragma unroll
        for (int i = 0; i < 8; i++) {
            int jj = i * 32 + lane;            // local float4 index 0..255
            float4 v = grow4[half * 256 + jj]; // coalesced LDG.128
            *(float4*)&sh[(jj >> 3) * HALF_PAD + ((jj & 7) << 2)] = v;
        }

        // ---- person projection: even warp's lanes 0..9 (once per row) ----
        if (half == 0 && lane < 10) {
            float aw = b1[lane];
            const float* pv = grow + p * WIRE_DIM;  // uniform-address gmem reads
#pragma unroll
            for (int k = 0; k < WIRE_DIM; k++)
                aw = fmaf(pv[k], s_w1top[k * 10 + lane], aw);
            s_aw[rowloc][lane] = aw;
        }
        __syncwarp();

        // ---- MLP: one wire per lane (wire = half*32 + lane) ----
        uint64_t acc[10];
#pragma unroll
        for (int h = 0; h < 10; h++) acc[h] = 0ull;

        const ulonglong2* rA = (const ulonglong2*)&sh[lane * HALF_PAD];
#pragma unroll
        for (int g = 0; g < 8; g++) {
            ulonglong2 v = rA[g];              // k = 4g..4g+3 packed as 2 f32x2
#pragma unroll
            for (int h = 0; h < 10; h++) {
                ulonglong2 w = *(const ulonglong2*)&s_w1b[h * 32 + g * 4];  // broadcast LDS.128
                FMA_F32X2(acc[h], v.x, w.x, acc[h]);
                FMA_F32X2(acc[h], v.y, w.y, acc[h]);
            }
        }

        __syncthreads();   // s_aw ready for both warps of the row

        // ---- head: hh = relu(lo + hi + aw), one logit per lane ----
        l = s_b2;
#pragma unroll
        for (int h = 0; h < 10; h++) {
            float2 a = upk2(acc[h]);
            l = fmaf(fmaxf(a.x + a.y + s_aw[rowloc][h], 0.f), s_w2[h], l);
        }
    } else {
        __syncthreads();
    }

    // ---- 2-warp log-softmax over 64 logits ----
    float m = l;
#pragma unroll
    for (int o = 16; o; o >>= 1) m = fmaxf(m, __shfl_xor_sync(0xffffffffu, m, o));
    if (lane == 0) s_m[warp] = m;
    if (active && (loc >> 5) == half && lane == (loc & 31)) s_sel[rowloc] = l;
    __syncthreads();

    m = fmaxf(s_m[rowloc * 2], s_m[rowloc * 2 + 1]);
    float s = __expf(l - m);
#pragma unroll
    for (int o = 16; o; o >>= 1) s += __shfl_xor_sync(0xffffffffu, s, o);
    if (lane == 0) s_s[warp] = s;
    __syncthreads();

    if (active && half == 0 && lane == 0) {
        float lse = m + __logf(s_s[rowloc * 2] + s_s[rowloc * 2 + 1]);
        out[row] = lse - s_sel[rowloc];        // loss = -(logit[loc] - lse)
    }
}

extern "C" void kernel_launch(void* const* d_in, const int* in_sizes, int n_in,
                              void* d_out, int out_size)
{
    const float* outputs = (const float*)d_in[0];
    const int*   tests   = (const int*)d_in[1];
    const float* W1      = (const float*)d_in[2];
    const float* b1      = (const float*)d_in[3];
    const float* W2      = (const float*)d_in[4];
    const float* b2      = (const float*)d_in[5];
    float* out = (float*)d_out;

    const int B = in_sizes[0] / ROW_ELEMS;
    const int grid = (B + ROWS_PER_BLOCK - 1) / ROWS_PER_BLOCK;
    isinone_loss_kernel<<<grid, THREADS>>>(outputs, tests, W1, b1, W2, b2, out, B);
}

// round 17
// speedup vs baseline: 1.3378x; 1.3378x over previous
#include <cuda_runtime.h>
#include <cstdint>

#define WIRE_DIM 32
#define NUM_WIRES 64
#define ROW_ELEMS (NUM_WIRES * WIRE_DIM)   // 2048
#define ROW_PAD 36                          // wire stride in smem floats (16B-aligned, conflict-free)
#define ROWS_PER_BLOCK 4
#define THREADS (32 * ROWS_PER_BLOCK)

// packed fp32x2 FMA (SASS FFMA2)
#define FMA_F32X2(d, a, b, c) \
    asm("fma.rn.f32x2 %0, %1, %2, %3;" : "=l"(d) : "l"(a), "l"(b), "l"(c))

__device__ __forceinline__ uint64_t pk2(float lo, float hi) {
    uint64_t r; asm("mov.b64 %0, {%1, %2};" : "=l"(r) : "f"(lo), "f"(hi)); return r;
}
__device__ __forceinline__ float2 upk2(uint64_t v) {
    float2 r; asm("mov.b64 {%0, %1}, %2;" : "=f"(r.x), "=f"(r.y) : "l"(v)); return r;
}

__global__ __launch_bounds__(THREADS)
void isinone_loss_kernel(const float* __restrict__ outputs,
                         const int* __restrict__ tests,      // int32 pairs (person, location)
                         const float* __restrict__ W1,
                         const float* __restrict__ b1,
                         const float* __restrict__ W2,
                         const float* __restrict__ b2,
                         float* __restrict__ out,
                         int B)
{
    // W1 bottom rows transposed, k-contiguous per h: s_w1b[h*32+k] = W1[(32+k)*10+h]
    __shared__ __align__(16) float s_w1b[10 * 32];
    // W1 top rows, original [k][h] layout (conflict-free lane reads for person proj)
    __shared__ __align__(16) float s_w1top[320];
    __shared__ __align__(16) float s_wires[ROWS_PER_BLOCK][NUM_WIRES * ROW_PAD];
    __shared__ float s_w2[10];
    __shared__ float s_b2;
    __shared__ float s_aw[ROWS_PER_BLOCK][10];   // b1 + person_vec @ W1_top

    const int tid = threadIdx.x;

    // ---- load weights (once per block) ----
    for (int i = tid; i < 320; i += THREADS) {
        s_w1top[i] = W1[i];                    // first 32 rows, as-is
        int h = i >> 5, k = i & 31;
        s_w1b[h * 32 + k] = W1[(32 + k) * 10 + h];
    }
    if (tid < 10) s_w2[tid] = W2[tid];
    if (tid == 0) s_b2 = b2[0];
    __syncthreads();

    const int warp = tid >> 5;
    const int lane = tid & 31;
    const int row  = blockIdx.x * ROWS_PER_BLOCK + warp;
    if (row >= B) return;   // B % ROWS_PER_BLOCK == 0 in practice; no barriers below

    const float*  grow  = outputs + (size_t)row * ROW_ELEMS;
    const float4* grow4 = (const float4*)grow;
    float* srow = s_wires[warp];

    const int p   = tests[2 * row + 0];
    const int loc = tests[2 * row + 1];

    // ---- async stage full row gmem -> smem (LDGSTS, no register residency) ----
    const uint32_t sbase = (uint32_t)__cvta_generic_to_shared(srow);
#pragma unroll
    for (int i = 0; i < 16; i++) {
        int j = i * 32 + lane;                 // float4 index 0..511, coalesced
        uint32_t dst = sbase + (uint32_t)(((j >> 3) * ROW_PAD + ((j & 7) << 2)) * 4);
        asm volatile("cp.async.cg.shared.global [%0], [%1], 16;"
                     :: "r"(dst), "l"(grow4 + j));
    }
    asm volatile("cp.async.commit_group;");

    // ---- person projection overlaps the async fill (lanes 0..9) ----
    // uniform-address gmem reads: 1 sector per load, broadcast to 10 lanes
    if (lane < 10) {
        float aw = b1[lane];
        const float* pv = grow + p * WIRE_DIM;
#pragma unroll
        for (int k = 0; k < WIRE_DIM; k++)
            aw = fmaf(pv[k], s_w1top[k * 10 + lane], aw);
        s_aw[warp][lane] = aw;
    }

    asm volatile("cp.async.wait_group 0;" ::: "memory");
    __syncwarp();

    // ---- main MLP: lane handles wires (lane) and (lane+32), packed f32x2 on k ----
    uint64_t acc0[10], acc1[10];
#pragma unroll
    for (int h = 0; h < 10; h++) {
        float a = s_aw[warp][h];
        acc0[h] = pk2(a, 0.f);                 // fold person+bias into lo half
        acc1[h] = pk2(a, 0.f);
    }

    const ulonglong2* rA = (const ulonglong2*)&srow[lane * ROW_PAD];
    const ulonglong2* rB = (const ulonglong2*)&srow[(lane + 32) * ROW_PAD];
#pragma unroll
    for (int g = 0; g < 8; g++) {
        ulonglong2 va = rA[g];                 // k = 4g..4g+3 packed as 2 f32x2
        ulonglong2 vb = rB[g];
#pragma unroll
        for (int h = 0; h < 10; h++) {
            ulonglong2 w = *(const ulonglong2*)&s_w1b[h * 32 + g * 4];  // broadcast LDS.128
            FMA_F32X2(acc0[h], va.x, w.x, acc0[h]);
            FMA_F32X2(acc0[h], va.y, w.y, acc0[h]);
            FMA_F32X2(acc1[h], vb.x, w.x, acc1[h]);
            FMA_F32X2(acc1[h], vb.y, w.y, acc1[h]);
        }
    }

    // ---- head: h = relu(lo + hi), logits ----
    float l0 = s_b2, l1 = s_b2;
#pragma unroll
    for (int h = 0; h < 10; h++) {
        float2 a0 = upk2(acc0[h]);
        float2 a1 = upk2(acc1[h]);
        l0 = fmaf(fmaxf(a0.x + a0.y, 0.f), s_w2[h], l0);
        l1 = fmaf(fmaxf(a1.x + a1.y, 0.f), s_w2[h], l1);
    }

    // ---- warp log-softmax over 64 logits (2 per lane) ----
    float m = fmaxf(l0, l1);
#pragma unroll
    for (int o = 16; o; o >>= 1) m = fmaxf(m, __shfl_xor_sync(0xffffffffu, m, o));
    float s = __expf(l0 - m) + __expf(l1 - m);
#pragma unroll
    for (int o = 16; o; o >>= 1) s += __shfl_xor_sync(0xffffffffu, s, o);
    float lse = m + __logf(s);

    float lsel = __shfl_sync(0xffffffffu, (loc < 32) ? l0 : l1, loc & 31);
    if (lane == 0) out[row] = lse - lsel;      // loss = -(logit[loc] - lse)
}

extern "C" void kernel_launch(void* const* d_in, const int* in_sizes, int n_in,
                              void* d_out, int out_size)
{
    const float* outputs = (const float*)d_in[0];
    const int*   tests   = (const int*)d_in[1];
    const float* W1      = (const float*)d_in[2];
    const float* b1      = (const float*)d_in[3];
    const float* W2      = (const float*)d_in[4];
    const float* b2      = (const float*)d_in[5];
    float* out = (float*)d_out;

    const int B = in_sizes[0] / ROW_ELEMS;
    const int grid = (B + ROWS_PER_BLOCK - 1) / ROWS_PER_BLOCK;
    isinone_loss_kernel<<<grid, THREADS>>>(outputs, tests, W1, b1, W2, b2, out, B);
}